// round 6
// baseline (speedup 1.0000x reference)
#include <cuda_runtime.h>
#include <math.h>

// ---------------- problem constants ----------------
#define NTOK 8192      // BATCH*SEQ tokens
#define HDIM 1024
#define IDIM 2048
#define NEXP 8
#define NSLOT (NTOK*2) // 16384 (token, expert) assignments

// ---------------- GEMM tiling ----------------
#define BM 128
#define BN 128
#define BK 16
#define MAXT 136       // max row tiles: 16384/128 + 8 experts partial

typedef unsigned long long u64;

// ---------------- device scratch (static, no allocs) ----------------
__device__ float g_H1[(size_t)NSLOT * IDIM];   // 128 MB  gelu(X @ Wfc^T) per slot-row
__device__ float g_Y2[(size_t)NSLOT * HDIM];   // 64 MB   H1 @ Wproj^T per slot-row
__device__ int   g_perm[NSLOT];                // slot-row -> token
__device__ float g_wt[NSLOT];                  // slot-row -> routing weight
__device__ int   g_slot[NSLOT];                // token*2+k -> slot-row (inverse map)
__device__ int   g_te[NSLOT];                  // token*2+k -> expert
__device__ float g_twt[NSLOT];                 // token*2+k -> weight
__device__ int   g_counts[NEXP];
__device__ int   g_offsets[NEXP];
__device__ int   g_cursors[NEXP];
__device__ int   g_numTiles;
__device__ int   g_tileE[MAXT];
__device__ int   g_tileRow0[MAXT];
__device__ int   g_tileRows[MAXT];

// ---------------- init ----------------
__global__ void k_init() {
    int i = threadIdx.x;
    if (i < NEXP) { g_counts[i] = 0; g_cursors[i] = 0; }
}

// ---------------- router: warp per token ----------------
__global__ void k_router(const float* __restrict__ X, const float* __restrict__ Wg,
                         float* __restrict__ logits, int write_logits) {
    int warp = threadIdx.x >> 5;
    int lane = threadIdx.x & 31;
    int t = blockIdx.x * (blockDim.x >> 5) + warp;
    if (t >= NTOK) return;
    const float* xp = X + (size_t)t * HDIM;
    float acc[NEXP];
#pragma unroll
    for (int e = 0; e < NEXP; e++) acc[e] = 0.f;
    for (int k = lane; k < HDIM; k += 32) {
        float xv = __ldg(xp + k);
#pragma unroll
        for (int e = 0; e < NEXP; e++) acc[e] = fmaf(xv, __ldg(Wg + e * HDIM + k), acc[e]);
    }
#pragma unroll
    for (int e = 0; e < NEXP; e++) {
        acc[e] += __shfl_xor_sync(0xffffffffu, acc[e], 16);
        acc[e] += __shfl_xor_sync(0xffffffffu, acc[e], 8);
        acc[e] += __shfl_xor_sync(0xffffffffu, acc[e], 4);
        acc[e] += __shfl_xor_sync(0xffffffffu, acc[e], 2);
        acc[e] += __shfl_xor_sync(0xffffffffu, acc[e], 1);
    }
    if (lane == 0) {
        if (write_logits) {
#pragma unroll
            for (int e = 0; e < NEXP; e++) logits[(size_t)t * NEXP + e] = acc[e];
        }
        // top-2 (first-occurrence tie-break, matches jax top_k)
        int i0 = 0;
#pragma unroll
        for (int e = 1; e < NEXP; e++) if (acc[e] > acc[i0]) i0 = e;
        int i1 = (i0 == 0) ? 1 : 0;
#pragma unroll
        for (int e = 0; e < NEXP; e++) if (e != i1 && e != i0 && acc[e] > acc[i1]) i1 = e;
        // normalized top-2 weights: p0/(p0+p1) = 1/(1+exp(l1-l0))
        float d  = expf(acc[i1] - acc[i0]);
        float w0 = 1.f / (1.f + d);
        float w1 = 1.f - w0;
        g_te[2 * t]     = i0; g_twt[2 * t]     = w0;
        g_te[2 * t + 1] = i1; g_twt[2 * t + 1] = w1;
        atomicAdd(&g_counts[i0], 1);
        atomicAdd(&g_counts[i1], 1);
    }
}

// ---------------- scan + tile schedule (tiny, 1 thread) ----------------
__global__ void k_scan() {
    int off = 0, t = 0;
    for (int e = 0; e < NEXP; e++) {
        g_offsets[e] = off;
        int c = g_counts[e];
        for (int r = 0; r < c; r += BM) {
            g_tileE[t]    = e;
            g_tileRow0[t] = off + r;
            g_tileRows[t] = (c - r < BM) ? (c - r) : BM;
            t++;
        }
        off += c;
    }
    g_numTiles = t;
}

// ---------------- scatter tokens into per-expert rows ----------------
__global__ void k_scatter() {
    int t = blockIdx.x * blockDim.x + threadIdx.x;
    if (t >= NTOK) return;
#pragma unroll
    for (int s = 0; s < 2; s++) {
        int e = g_te[2 * t + s];
        int pos = g_offsets[e] + atomicAdd(&g_cursors[e], 1);
        g_perm[pos] = t;
        g_wt[pos]   = g_twt[2 * t + s];
        g_slot[2 * t + s] = pos;
    }
}

// packed dual-FMA: acc.{lo,hi} += a.{lo,hi} * b.{lo,hi}
__device__ __forceinline__ void fma2(u64& acc, u64 a, u64 b) {
    asm("fma.rn.f32x2 %0, %1, %2, %0;" : "+l"(acc) : "l"(a), "l"(b));
}
// duplicate a scalar float into both lanes of a packed f32x2
__device__ __forceinline__ u64 dup2(float a) {
    u64 r;
    unsigned int ai = __float_as_uint(a);
    asm("mov.b64 %0, {%1, %1};" : "=l"(r) : "r"(ai));
    return r;
}

// ---------------- GEMM1: H1 = gelu(gather(X) @ Wfc[e]^T), K=1024 ----------------
__global__ __launch_bounds__(256) void k_gemm1(const float* __restrict__ X,
                                               const float* __restrict__ Wfc) {
    int tile = blockIdx.x;
    if (tile >= g_numTiles) return;
    int e = g_tileE[tile], row0 = g_tileRow0[tile], rows = g_tileRows[tile];
    int col0 = blockIdx.y * BN;

    __shared__ __align__(16) float As[BK][BM + 4];
    __shared__ __align__(16) float Bs[BK][BN + 4];
    __shared__ int rowTok[BM];

    int tid = threadIdx.x;
    int tx = tid & 15, ty = tid >> 4;
    const float* Bp = Wfc + (size_t)e * IDIM * HDIM + (size_t)col0 * HDIM;

    if (tid < BM) rowTok[tid] = (tid < rows) ? g_perm[row0 + tid] : -1;
    __syncthreads();

    u64 acc2[8][4];   // 8 rows x 4 packed col-pairs
#pragma unroll
    for (int i = 0; i < 8; i++)
#pragma unroll
        for (int j = 0; j < 4; j++) acc2[i][j] = 0ull;

    for (int k0 = 0; k0 < HDIM; k0 += BK) {
#pragma unroll
        for (int i = 0; i < 2; i++) {
            int idx = tid + i * 256;        // 0..511 -> 128 rows x 4 float4
            int m = idx >> 2, k4 = idx & 3;
            float4 v = make_float4(0.f, 0.f, 0.f, 0.f);
            int tok = rowTok[m];
            if (tok >= 0) v = *(const float4*)(X + (size_t)tok * HDIM + k0 + k4 * 4);
            As[k4 * 4 + 0][m] = v.x; As[k4 * 4 + 1][m] = v.y;
            As[k4 * 4 + 2][m] = v.z; As[k4 * 4 + 3][m] = v.w;
            float4 w = *(const float4*)(Bp + (size_t)m * HDIM + k0 + k4 * 4);
            Bs[k4 * 4 + 0][m] = w.x; Bs[k4 * 4 + 1][m] = w.y;
            Bs[k4 * 4 + 2][m] = w.z; Bs[k4 * 4 + 3][m] = w.w;
        }
        __syncthreads();
#pragma unroll
        for (int k = 0; k < BK; k++) {
            float a[8];
            *(float4*)&a[0] = *(const float4*)&As[k][ty * 8];
            *(float4*)&a[4] = *(const float4*)&As[k][ty * 8 + 4];
            u64 b2[4];
            *(float4*)&b2[0] = *(const float4*)&Bs[k][tx * 8];
            *(float4*)&b2[2] = *(const float4*)&Bs[k][tx * 8 + 4];
            u64 a2[8];
#pragma unroll
            for (int i = 0; i < 8; i++) a2[i] = dup2(a[i]);
#pragma unroll
            for (int i = 0; i < 8; i++)
#pragma unroll
                for (int j = 0; j < 4; j++) fma2(acc2[i][j], a2[i], b2[j]);
        }
        __syncthreads();
    }
#pragma unroll
    for (int i = 0; i < 8; i++) {
        int m = ty * 8 + i;
        if (m < rows) {
            float* op = g_H1 + (size_t)(row0 + m) * IDIM + col0 + tx * 8;
#pragma unroll
            for (int j = 0; j < 4; j++) {
                float2 v = *(float2*)&acc2[i][j];
                op[2 * j + 0] = 0.5f * v.x * (1.f + erff(v.x * 0.70710678118654752f));
                op[2 * j + 1] = 0.5f * v.y * (1.f + erff(v.y * 0.70710678118654752f));
            }
        }
    }
}

// ---------------- GEMM2: Y2 = H1 @ Wproj[e]^T, K=2048 ----------------
__global__ __launch_bounds__(256) void k_gemm2(const float* __restrict__ Wproj) {
    int tile = blockIdx.x;
    if (tile >= g_numTiles) return;
    int e = g_tileE[tile], row0 = g_tileRow0[tile], rows = g_tileRows[tile];
    int col0 = blockIdx.y * BN;

    __shared__ __align__(16) float As[BK][BM + 4];
    __shared__ __align__(16) float Bs[BK][BN + 4];

    int tid = threadIdx.x;
    int tx = tid & 15, ty = tid >> 4;
    const float* Ap = g_H1 + (size_t)row0 * IDIM;
    const float* Bp = Wproj + (size_t)e * HDIM * IDIM + (size_t)col0 * IDIM;

    u64 acc2[8][4];
#pragma unroll
    for (int i = 0; i < 8; i++)
#pragma unroll
        for (int j = 0; j < 4; j++) acc2[i][j] = 0ull;

    for (int k0 = 0; k0 < IDIM; k0 += BK) {
#pragma unroll
        for (int i = 0; i < 2; i++) {
            int idx = tid + i * 256;
            int m = idx >> 2, k4 = idx & 3;
            float4 v = make_float4(0.f, 0.f, 0.f, 0.f);
            if (m < rows) v = *(const float4*)(Ap + (size_t)m * IDIM + k0 + k4 * 4);
            As[k4 * 4 + 0][m] = v.x; As[k4 * 4 + 1][m] = v.y;
            As[k4 * 4 + 2][m] = v.z; As[k4 * 4 + 3][m] = v.w;
            float4 w = *(const float4*)(Bp + (size_t)m * IDIM + k0 + k4 * 4);
            Bs[k4 * 4 + 0][m] = w.x; Bs[k4 * 4 + 1][m] = w.y;
            Bs[k4 * 4 + 2][m] = w.z; Bs[k4 * 4 + 3][m] = w.w;
        }
        __syncthreads();
#pragma unroll
        for (int k = 0; k < BK; k++) {
            float a[8];
            *(float4*)&a[0] = *(const float4*)&As[k][ty * 8];
            *(float4*)&a[4] = *(const float4*)&As[k][ty * 8 + 4];
            u64 b2[4];
            *(float4*)&b2[0] = *(const float4*)&Bs[k][tx * 8];
            *(float4*)&b2[2] = *(const float4*)&Bs[k][tx * 8 + 4];
            u64 a2[8];
#pragma unroll
            for (int i = 0; i < 8; i++) a2[i] = dup2(a[i]);
#pragma unroll
            for (int i = 0; i < 8; i++)
#pragma unroll
                for (int j = 0; j < 4; j++) fma2(acc2[i][j], a2[i], b2[j]);
        }
        __syncthreads();
    }
#pragma unroll
    for (int i = 0; i < 8; i++) {
        int m = ty * 8 + i;
        if (m < rows) {
            float* op = g_Y2 + (size_t)(row0 + m) * HDIM + col0 + tx * 8;
#pragma unroll
            for (int j = 0; j < 4; j++) {
                float2 v = *(float2*)&acc2[i][j];
                op[2 * j + 0] = v.x;
                op[2 * j + 1] = v.y;
            }
        }
    }
}

// ---------------- combine: out[t] = w0*Y2[slot0] + w1*Y2[slot1] ----------------
__global__ void k_combine(float* __restrict__ out) {
    int i4 = blockIdx.x * blockDim.x + threadIdx.x;   // over NTOK*HDIM/4
    if (i4 >= NTOK * (HDIM / 4)) return;
    int t  = i4 / (HDIM / 4);
    int h4 = i4 % (HDIM / 4);
    int p0 = g_slot[2 * t], p1 = g_slot[2 * t + 1];
    float w0 = g_wt[p0], w1 = g_wt[p1];
    float4 a = *(const float4*)(g_Y2 + (size_t)p0 * HDIM + h4 * 4);
    float4 b = *(const float4*)(g_Y2 + (size_t)p1 * HDIM + h4 * 4);
    float4 o;
    o.x = fmaf(w0, a.x, w1 * b.x);
    o.y = fmaf(w0, a.y, w1 * b.y);
    o.z = fmaf(w0, a.z, w1 * b.z);
    o.w = fmaf(w0, a.w, w1 * b.w);
    *((float4*)out + i4) = o;
}

// ---------------- launch ----------------
extern "C" void kernel_launch(void* const* d_in, const int* in_sizes, int n_in,
                              void* d_out, int out_size) {
    const float* X     = (const float*)d_in[0];   // [2,4096,1024]
    const float* Wg    = (const float*)d_in[1];   // [8,1024]
    const float* Wfc   = (const float*)d_in[2];   // [8,2048,1024]
    const float* Wproj = (const float*)d_in[3];   // [8,1024,2048]
    float* out = (float*)d_out;

    int write_logits = (out_size >= NTOK * HDIM + NTOK * NEXP) ? 1 : 0;
    float* logits = out + (size_t)NTOK * HDIM;

    k_init<<<1, 32>>>();
    k_router<<<NTOK / 8, 256>>>(X, Wg, logits, write_logits);
    k_scan<<<1, 1>>>();
    k_scatter<<<NTOK / 256, 256>>>();
    k_gemm1<<<dim3(MAXT, IDIM / BN), 256>>>(X, Wfc);
    k_gemm2<<<dim3(MAXT, HDIM / BN), 256>>>(Wproj);
    k_combine<<<(NTOK * (HDIM / 4) + 255) / 256, 256>>>(out);
}

// round 8
// speedup vs baseline: 2.1623x; 2.1623x over previous
#include <cuda_runtime.h>
#include <cuda_bf16.h>
#include <mma.h>
#include <math.h>

using namespace nvcuda;

// ---------------- problem constants ----------------
#define NTOK 8192
#define HDIM 1024
#define IDIM 2048
#define NEXP 8
#define NSLOT (NTOK*2)

#define BM 128
#define BN 128
#define BK 32             // k-chunk (two k16 wmma steps)
#define MAXT 136

#define APITCH 40         // bf16 elems; 80B row stride -> conflict-free ldsm
#define BPITCH 40
#define SPITCH 132        // float stage pitch

// smem layout (bytes)
#define SM_ROWTOK 0       // 128 ints
#define SM_AHI 1024
#define TILE_B (128*APITCH*2)          // 10240
#define SM_ALO (SM_AHI + TILE_B)
#define SM_BHI (SM_ALO + TILE_B)
#define SM_BLO (SM_BHI + TILE_B)
#define SM_END (SM_BLO + TILE_B)       // 41984
#define STAGE_B (128*SPITCH*4)         // 67584
#define DSMEM (STAGE_B > SM_END ? STAGE_B : SM_END)

typedef unsigned int u32;

// ---------------- device scratch ----------------
__device__ __nv_bfloat16 g_Xhi[(size_t)NTOK * HDIM];
__device__ __nv_bfloat16 g_Xlo[(size_t)NTOK * HDIM];
__device__ __nv_bfloat16 g_Wfh[(size_t)NEXP * IDIM * HDIM];
__device__ __nv_bfloat16 g_Wfl[(size_t)NEXP * IDIM * HDIM];
__device__ __nv_bfloat16 g_Wph[(size_t)NEXP * HDIM * IDIM];
__device__ __nv_bfloat16 g_Wpl[(size_t)NEXP * HDIM * IDIM];
__device__ __nv_bfloat16 g_H1h[(size_t)NSLOT * IDIM];
__device__ __nv_bfloat16 g_H1l[(size_t)NSLOT * IDIM];
__device__ float g_Y2[(size_t)NSLOT * HDIM];
__device__ int   g_perm[NSLOT];
__device__ float g_wt[NSLOT];
__device__ int   g_slot[NSLOT];
__device__ int   g_te[NSLOT];
__device__ float g_twt[NSLOT];
__device__ int   g_counts[NEXP];
__device__ int   g_offsets[NEXP];
__device__ int   g_cursors[NEXP];
__device__ int   g_numTiles;
__device__ int   g_tileE[MAXT];
__device__ int   g_tileRow0[MAXT];
__device__ int   g_tileRows[MAXT];

// ---------------- small kernels ----------------
__global__ void k_init() {
    int i = threadIdx.x;
    if (i < NEXP) { g_counts[i] = 0; g_cursors[i] = 0; }
}

__global__ void k_split(const float* __restrict__ s, __nv_bfloat16* __restrict__ hi,
                        __nv_bfloat16* __restrict__ lo, int n4) {
    int i = blockIdx.x * blockDim.x + threadIdx.x;
    if (i >= n4) return;
    float4 v = ((const float4*)s)[i];
    __nv_bfloat16 h0 = __float2bfloat16(v.x), h1 = __float2bfloat16(v.y);
    __nv_bfloat16 h2 = __float2bfloat16(v.z), h3 = __float2bfloat16(v.w);
    __nv_bfloat16 l0 = __float2bfloat16(v.x - __bfloat162float(h0));
    __nv_bfloat16 l1 = __float2bfloat16(v.y - __bfloat162float(h1));
    __nv_bfloat16 l2 = __float2bfloat16(v.z - __bfloat162float(h2));
    __nv_bfloat16 l3 = __float2bfloat16(v.w - __bfloat162float(h3));
    uint2 ph, pl;
    ph.x = (u32)__bfloat16_as_ushort(h0) | ((u32)__bfloat16_as_ushort(h1) << 16);
    ph.y = (u32)__bfloat16_as_ushort(h2) | ((u32)__bfloat16_as_ushort(h3) << 16);
    pl.x = (u32)__bfloat16_as_ushort(l0) | ((u32)__bfloat16_as_ushort(l1) << 16);
    pl.y = (u32)__bfloat16_as_ushort(l2) | ((u32)__bfloat16_as_ushort(l3) << 16);
    ((uint2*)hi)[i] = ph;
    ((uint2*)lo)[i] = pl;
}

__global__ void k_router(const float* __restrict__ X, const float* __restrict__ Wg,
                         float* __restrict__ logits, int write_logits) {
    int warp = threadIdx.x >> 5, lane = threadIdx.x & 31;
    int t = blockIdx.x * (blockDim.x >> 5) + warp;
    if (t >= NTOK) return;
    const float* xp = X + (size_t)t * HDIM;
    float acc[NEXP];
#pragma unroll
    for (int e = 0; e < NEXP; e++) acc[e] = 0.f;
    for (int k = lane; k < HDIM; k += 32) {
        float xv = __ldg(xp + k);
#pragma unroll
        for (int e = 0; e < NEXP; e++) acc[e] = fmaf(xv, __ldg(Wg + e * HDIM + k), acc[e]);
    }
#pragma unroll
    for (int e = 0; e < NEXP; e++) {
        acc[e] += __shfl_xor_sync(0xffffffffu, acc[e], 16);
        acc[e] += __shfl_xor_sync(0xffffffffu, acc[e], 8);
        acc[e] += __shfl_xor_sync(0xffffffffu, acc[e], 4);
        acc[e] += __shfl_xor_sync(0xffffffffu, acc[e], 2);
        acc[e] += __shfl_xor_sync(0xffffffffu, acc[e], 1);
    }
    if (lane == 0) {
        if (write_logits) {
#pragma unroll
            for (int e = 0; e < NEXP; e++) logits[(size_t)t * NEXP + e] = acc[e];
        }
        int i0 = 0;
#pragma unroll
        for (int e = 1; e < NEXP; e++) if (acc[e] > acc[i0]) i0 = e;
        int i1 = (i0 == 0) ? 1 : 0;
#pragma unroll
        for (int e = 0; e < NEXP; e++) if (e != i1 && e != i0 && acc[e] > acc[i1]) i1 = e;
        float d  = expf(acc[i1] - acc[i0]);
        float w0 = 1.f / (1.f + d);
        g_te[2*t] = i0;   g_twt[2*t] = w0;
        g_te[2*t+1] = i1; g_twt[2*t+1] = 1.f - w0;
        atomicAdd(&g_counts[i0], 1);
        atomicAdd(&g_counts[i1], 1);
    }
}

__global__ void k_scan() {
    int off = 0, t = 0;
    for (int e = 0; e < NEXP; e++) {
        g_offsets[e] = off;
        int c = g_counts[e];
        for (int r = 0; r < c; r += BM) {
            g_tileE[t] = e; g_tileRow0[t] = off + r;
            g_tileRows[t] = (c - r < BM) ? (c - r) : BM;
            t++;
        }
        off += c;
    }
    g_numTiles = t;
}

__global__ void k_scatter() {
    int t = blockIdx.x * blockDim.x + threadIdx.x;
    if (t >= NTOK) return;
#pragma unroll
    for (int s = 0; s < 2; s++) {
        int e = g_te[2*t + s];
        int pos = g_offsets[e] + atomicAdd(&g_cursors[e], 1);
        g_perm[pos] = t;
        g_wt[pos] = g_twt[2*t + s];
        g_slot[2*t + s] = pos;
    }
}

// ---------------- wmma GEMM core (shared by both GEMMs) ----------------
// 8 warps: warp_m in {0,1} covers 64 M-rows, warp_n in {0..3} covers 32 N-cols.
// acc[4][2] frags (fp32). Per k16: 3-term compensated bf16 MMA.
template <bool GATHER>
__device__ __forceinline__ void gemm_tile(
    char* smem, int tid,
    const __nv_bfloat16* __restrict__ Ah, const __nv_bfloat16* __restrict__ Al,
    size_t a_stride,            // row stride of A source (elems)
    const int* rowTok,          // GATHER: token per m-row (or -1); else nullptr
    int rows,                   // valid A rows (!GATHER path masks m >= rows)
    const __nv_bfloat16* __restrict__ Bh, const __nv_bfloat16* __restrict__ Bl,
    size_t b_stride, int kdim,
    wmma::fragment<wmma::accumulator, 16, 16, 16, float> (&acc)[4][2])
{
    int wid = tid >> 5;
    int warp_m = wid & 1, warp_n = wid >> 1;
    __nv_bfloat16* As_h = (__nv_bfloat16*)(smem + SM_AHI);
    __nv_bfloat16* As_l = (__nv_bfloat16*)(smem + SM_ALO);
    __nv_bfloat16* Bs_h = (__nv_bfloat16*)(smem + SM_BHI);
    __nv_bfloat16* Bs_l = (__nv_bfloat16*)(smem + SM_BLO);

#pragma unroll
    for (int i = 0; i < 4; i++)
#pragma unroll
        for (int j = 0; j < 2; j++) wmma::fill_fragment(acc[i][j], 0.f);

    for (int k0 = 0; k0 < kdim; k0 += BK) {
        // load A/B chunk: 128 rows x 32 cols each, uint4 = 8 bf16
#pragma unroll
        for (int t4 = 0; t4 < 2; t4++) {
            int u = tid + t4 * 256;          // 0..511
            int m = u >> 2, kb = (u & 3) * 8;
            size_t so = (size_t)m * APITCH + k0 % 1 /*0*/ + kb;  // smem offset elems
            uint4 vh = make_uint4(0,0,0,0), vl = vh;
            if (GATHER) {
                int tok = rowTok[m];
                if (tok >= 0) {
                    size_t o = (size_t)tok * a_stride + k0 + kb;
                    vh = *(const uint4*)(Ah + o);
                    vl = *(const uint4*)(Al + o);
                }
            } else {
                if (m < rows) {
                    size_t o = (size_t)m * a_stride + k0 + kb;
                    vh = *(const uint4*)(Ah + o);
                    vl = *(const uint4*)(Al + o);
                }
            }
            *(uint4*)(As_h + so) = vh;
            *(uint4*)(As_l + so) = vl;
            size_t ob = (size_t)m * b_stride + k0 + kb;
            *(uint4*)(Bs_h + (size_t)m * BPITCH + kb) = *(const uint4*)(Bh + ob);
            *(uint4*)(Bs_l + (size_t)m * BPITCH + kb) = *(const uint4*)(Bl + ob);
        }
        __syncthreads();

#pragma unroll
        for (int ks = 0; ks < 2; ks++) {
            wmma::fragment<wmma::matrix_b, 16, 16, 16, __nv_bfloat16, wmma::col_major> bh[2], bl[2];
#pragma unroll
            for (int j = 0; j < 2; j++) {
                int n = warp_n * 32 + j * 16;
                wmma::load_matrix_sync(bh[j], Bs_h + (size_t)n * BPITCH + ks * 16, BPITCH);
                wmma::load_matrix_sync(bl[j], Bs_l + (size_t)n * BPITCH + ks * 16, BPITCH);
            }
#pragma unroll
            for (int i = 0; i < 4; i++) {
                int m = warp_m * 64 + i * 16;
                wmma::fragment<wmma::matrix_a, 16, 16, 16, __nv_bfloat16, wmma::row_major> ah, al;
                wmma::load_matrix_sync(ah, As_h + (size_t)m * APITCH + ks * 16, APITCH);
                wmma::load_matrix_sync(al, As_l + (size_t)m * APITCH + ks * 16, APITCH);
#pragma unroll
                for (int j = 0; j < 2; j++) {
                    wmma::mma_sync(acc[i][j], ah, bh[j], acc[i][j]);
                    wmma::mma_sync(acc[i][j], ah, bl[j], acc[i][j]);
                    wmma::mma_sync(acc[i][j], al, bh[j], acc[i][j]);
                }
            }
        }
        __syncthreads();
    }
}

// ---------------- GEMM1: H1 = gelu(gather(X) @ Wfc[e]^T) ----------------
__global__ __launch_bounds__(256, 2) void k_gemm1(int) {
    int tile = blockIdx.x;
    if (tile >= g_numTiles) return;
    int e = g_tileE[tile], row0 = g_tileRow0[tile], rows = g_tileRows[tile];
    int col0 = blockIdx.y * BN;

    extern __shared__ char smem[];
    int tid = threadIdx.x, wid = tid >> 5;
    int warp_m = wid & 1, warp_n = wid >> 1;

    int* rowTok = (int*)(smem + SM_ROWTOK);
    if (tid < BM) rowTok[tid] = (tid < rows) ? g_perm[row0 + tid] : -1;
    __syncthreads();

    wmma::fragment<wmma::accumulator, 16, 16, 16, float> acc[4][2];
    const __nv_bfloat16* Bh = g_Wfh + ((size_t)e * IDIM + col0) * HDIM;
    const __nv_bfloat16* Bl = g_Wfl + ((size_t)e * IDIM + col0) * HDIM;
    gemm_tile<true>(smem, tid, g_Xhi, g_Xlo, HDIM, rowTok, rows, Bh, Bl, HDIM, HDIM, acc);

    // stage to smem (float), then gelu + bf16 split + masked coalesced store
    float* st = (float*)smem;   // 128 x SPITCH
    __syncthreads();
#pragma unroll
    for (int i = 0; i < 4; i++)
#pragma unroll
        for (int j = 0; j < 2; j++)
            wmma::store_matrix_sync(st + (size_t)(warp_m * 64 + i * 16) * SPITCH
                                       + warp_n * 32 + j * 16,
                                    acc[i][j], SPITCH, wmma::mem_row_major);
    __syncthreads();
    for (int u = tid; u < 128 * 16; u += 256) {   // 8 cols per unit
        int m = u >> 4, q = (u & 15) * 8;
        if (m < rows) {
            __nv_bfloat16 h8[8], l8[8];
#pragma unroll
            for (int c = 0; c < 8; c++) {
                float v = st[(size_t)m * SPITCH + q + c];
                float g = 0.5f * v * (1.f + erff(v * 0.70710678118654752f));
                __nv_bfloat16 h = __float2bfloat16(g);
                h8[c] = h;
                l8[c] = __float2bfloat16(g - __bfloat162float(h));
            }
            size_t o = (size_t)(row0 + m) * IDIM + col0 + q;
            *(uint4*)(g_H1h + o) = *(const uint4*)h8;
            *(uint4*)(g_H1l + o) = *(const uint4*)l8;
        }
    }
}

// ---------------- GEMM2: Y2 = H1 @ Wproj[e]^T ----------------
__global__ __launch_bounds__(256, 2) void k_gemm2(int) {
    int tile = blockIdx.x;
    if (tile >= g_numTiles) return;
    int e = g_tileE[tile], row0 = g_tileRow0[tile], rows = g_tileRows[tile];
    int col0 = blockIdx.y * BN;

    extern __shared__ char smem[];
    int tid = threadIdx.x, wid = tid >> 5;
    int warp_m = wid & 1, warp_n = wid >> 1;

    wmma::fragment<wmma::accumulator, 16, 16, 16, float> acc[4][2];
    const __nv_bfloat16* Ah = g_H1h + (size_t)row0 * IDIM;
    const __nv_bfloat16* Al = g_H1l + (size_t)row0 * IDIM;
    const __nv_bfloat16* Bh = g_Wph + ((size_t)e * HDIM + col0) * IDIM;
    const __nv_bfloat16* Bl = g_Wpl + ((size_t)e * HDIM + col0) * IDIM;
    gemm_tile<false>(smem, tid, Ah, Al, IDIM, nullptr, rows, Bh, Bl, IDIM, IDIM, acc);

    float* st = (float*)smem;
    __syncthreads();
#pragma unroll
    for (int i = 0; i < 4; i++)
#pragma unroll
        for (int j = 0; j < 2; j++)
            wmma::store_matrix_sync(st + (size_t)(warp_m * 64 + i * 16) * SPITCH
                                       + warp_n * 32 + j * 16,
                                    acc[i][j], SPITCH, wmma::mem_row_major);
    __syncthreads();
    for (int u = tid; u < 128 * 32; u += 256) {   // 4 floats per unit
        int m = u >> 5, q = (u & 31) * 4;
        if (m < rows) {
            size_t o = (size_t)(row0 + m) * HDIM + col0 + q;
            *(uint4*)(g_Y2 + o) = *(const uint4*)(st + (size_t)m * SPITCH + q);
        }
    }
}

// ---------------- combine ----------------
__global__ void k_combine(float* __restrict__ out) {
    int i4 = blockIdx.x * blockDim.x + threadIdx.x;
    if (i4 >= NTOK * (HDIM / 4)) return;
    int t = i4 / (HDIM / 4), h4 = i4 % (HDIM / 4);
    int p0 = g_slot[2*t], p1 = g_slot[2*t + 1];
    float w0 = g_wt[p0], w1 = g_wt[p1];
    float4 a = *(const float4*)(g_Y2 + (size_t)p0 * HDIM + h4 * 4);
    float4 b = *(const float4*)(g_Y2 + (size_t)p1 * HDIM + h4 * 4);
    float4 o;
    o.x = fmaf(w0, a.x, w1 * b.x);
    o.y = fmaf(w0, a.y, w1 * b.y);
    o.z = fmaf(w0, a.z, w1 * b.z);
    o.w = fmaf(w0, a.w, w1 * b.w);
    *((float4*)out + i4) = o;
}

// ---------------- launch ----------------
extern "C" void kernel_launch(void* const* d_in, const int* in_sizes, int n_in,
                              void* d_out, int out_size) {
    const float* X     = (const float*)d_in[0];
    const float* Wg    = (const float*)d_in[1];
    const float* Wfc   = (const float*)d_in[2];
    const float* Wproj = (const float*)d_in[3];
    float* out = (float*)d_out;

    int write_logits = (out_size >= NTOK * HDIM + NTOK * NEXP) ? 1 : 0;
    float* logits = out + (size_t)NTOK * HDIM;

    static int attr_done = 0;
    if (!attr_done) {
        cudaFuncSetAttribute(k_gemm1, cudaFuncAttributeMaxDynamicSharedMemorySize, DSMEM);
        cudaFuncSetAttribute(k_gemm2, cudaFuncAttributeMaxDynamicSharedMemorySize, DSMEM);
        attr_done = 1;
    }

    __nv_bfloat16 *xh, *xl, *wfh, *wfl, *wph, *wpl;
    cudaGetSymbolAddress((void**)&xh,  g_Xhi);  cudaGetSymbolAddress((void**)&xl,  g_Xlo);
    cudaGetSymbolAddress((void**)&wfh, g_Wfh);  cudaGetSymbolAddress((void**)&wfl, g_Wfl);
    cudaGetSymbolAddress((void**)&wph, g_Wph);  cudaGetSymbolAddress((void**)&wpl, g_Wpl);

    k_init<<<1, 32>>>();
    {
        int n4 = NTOK * HDIM / 4;
        k_split<<<(n4 + 255) / 256, 256>>>(X, xh, xl, n4);
    }
    {
        int n4 = NEXP * IDIM * HDIM / 4;
        k_split<<<(n4 + 255) / 256, 256>>>(Wfc, wfh, wfl, n4);
        k_split<<<(n4 + 255) / 256, 256>>>(Wproj, wph, wpl, n4);
    }
    k_router<<<NTOK / 8, 256>>>(X, Wg, logits, write_logits);
    k_scan<<<1, 1>>>();
    k_scatter<<<NTOK / 256, 256>>>();
    k_gemm1<<<dim3(MAXT, IDIM / BN), 256, DSMEM>>>(0);
    k_gemm2<<<dim3(MAXT, HDIM / BN), 256, DSMEM>>>(0);
    k_combine<<<(NTOK * (HDIM / 4) + 255) / 256, 256>>>(out);
}

// round 10
// speedup vs baseline: 2.3750x; 1.0984x over previous
#include <cuda_runtime.h>
#include <cuda_bf16.h>
#include <mma.h>
#include <math.h>

using namespace nvcuda;

// ---------------- problem constants ----------------
#define NTOK 8192
#define HDIM 1024
#define IDIM 2048
#define NEXP 8
#define NSLOT (NTOK*2)

#define BM 128
#define BN 128
#define BK 32             // k-chunk (two k16 wmma steps)
#define MAXT 136

#define APITCH 40         // bf16 elems; 80B row stride -> conflict-free ldsm
#define BPITCH 40
#define SPITCH 132        // float stage pitch (epilogue)

// double-buffered smem layout (bytes)
#define SM_ROWTOK 0       // 128 ints
#define SM_STG0   1024
#define TILE_B    (128*APITCH*2)       // 10240 per operand tile
#define STG_SZ    (4*TILE_B)           // 40960 per stage (Ahi,Alo,Bhi,Blo)
#define OFF_AH 0
#define OFF_AL (1*TILE_B)
#define OFF_BH (2*TILE_B)
#define OFF_BL (3*TILE_B)
#define DSMEM (SM_STG0 + 2*STG_SZ)     // 82944; epilogue float stage (67584) fits inside

typedef unsigned int u32;

// ---------------- device scratch ----------------
__device__ __nv_bfloat16 g_Xhi[(size_t)NTOK * HDIM];
__device__ __nv_bfloat16 g_Xlo[(size_t)NTOK * HDIM];
__device__ __nv_bfloat16 g_Wfh[(size_t)NEXP * IDIM * HDIM];
__device__ __nv_bfloat16 g_Wfl[(size_t)NEXP * IDIM * HDIM];
__device__ __nv_bfloat16 g_Wph[(size_t)NEXP * HDIM * IDIM];
__device__ __nv_bfloat16 g_Wpl[(size_t)NEXP * HDIM * IDIM];
__device__ __nv_bfloat16 g_H1h[(size_t)NSLOT * IDIM];
__device__ __nv_bfloat16 g_H1l[(size_t)NSLOT * IDIM];
__device__ float g_Y2[(size_t)NSLOT * HDIM];
__device__ int   g_perm[NSLOT];
__device__ float g_wt[NSLOT];
__device__ int   g_slot[NSLOT];
__device__ int   g_te[NSLOT];
__device__ float g_twt[NSLOT];
__device__ int   g_counts[NEXP];
__device__ int   g_offsets[NEXP];
__device__ int   g_cursors[NEXP];
__device__ int   g_numTiles;
__device__ int   g_tileE[MAXT];
__device__ int   g_tileRow0[MAXT];
__device__ int   g_tileRows[MAXT];

// ---------------- cp.async helpers (base sm_103 safe: LDGSTS, sm_80+) ----------------
__device__ __forceinline__ u32 smem_u32(const void* p) {
    u32 a;
    asm("{ .reg .u64 t; cvta.to.shared.u64 t, %1; cvt.u32.u64 %0, t; }" : "=r"(a) : "l"(p));
    return a;
}
__device__ __forceinline__ void cpa16(u32 dst, const void* src, u32 srcsz) {
    asm volatile("cp.async.cg.shared.global [%0], [%1], 16, %2;"
                 :: "r"(dst), "l"(src), "r"(srcsz) : "memory");
}
__device__ __forceinline__ void cpa_commit() {
    asm volatile("cp.async.commit_group;" ::: "memory");
}
template <int N>
__device__ __forceinline__ void cpa_wait() {
    asm volatile("cp.async.wait_group %0;" :: "n"(N) : "memory");
}

// ---------------- small kernels ----------------
__global__ void k_init() {
    int i = threadIdx.x;
    if (i < NEXP) { g_counts[i] = 0; g_cursors[i] = 0; }
}

__global__ void k_split(const float* __restrict__ s, __nv_bfloat16* __restrict__ hi,
                        __nv_bfloat16* __restrict__ lo, int n4) {
    int i = blockIdx.x * blockDim.x + threadIdx.x;
    if (i >= n4) return;
    float4 v = ((const float4*)s)[i];
    __nv_bfloat16 h0 = __float2bfloat16(v.x), h1 = __float2bfloat16(v.y);
    __nv_bfloat16 h2 = __float2bfloat16(v.z), h3 = __float2bfloat16(v.w);
    __nv_bfloat16 l0 = __float2bfloat16(v.x - __bfloat162float(h0));
    __nv_bfloat16 l1 = __float2bfloat16(v.y - __bfloat162float(h1));
    __nv_bfloat16 l2 = __float2bfloat16(v.z - __bfloat162float(h2));
    __nv_bfloat16 l3 = __float2bfloat16(v.w - __bfloat162float(h3));
    uint2 ph, pl;
    ph.x = (u32)__bfloat16_as_ushort(h0) | ((u32)__bfloat16_as_ushort(h1) << 16);
    ph.y = (u32)__bfloat16_as_ushort(h2) | ((u32)__bfloat16_as_ushort(h3) << 16);
    pl.x = (u32)__bfloat16_as_ushort(l0) | ((u32)__bfloat16_as_ushort(l1) << 16);
    pl.y = (u32)__bfloat16_as_ushort(l2) | ((u32)__bfloat16_as_ushort(l3) << 16);
    ((uint2*)hi)[i] = ph;
    ((uint2*)lo)[i] = pl;
}

__global__ void k_router(const float* __restrict__ X, const float* __restrict__ Wg,
                         float* __restrict__ logits, int write_logits) {
    int warp = threadIdx.x >> 5, lane = threadIdx.x & 31;
    int t = blockIdx.x * (blockDim.x >> 5) + warp;
    if (t >= NTOK) return;
    const float* xp = X + (size_t)t * HDIM;
    float acc[NEXP];
#pragma unroll
    for (int e = 0; e < NEXP; e++) acc[e] = 0.f;
    for (int k = lane; k < HDIM; k += 32) {
        float xv = __ldg(xp + k);
#pragma unroll
        for (int e = 0; e < NEXP; e++) acc[e] = fmaf(xv, __ldg(Wg + e * HDIM + k), acc[e]);
    }
#pragma unroll
    for (int e = 0; e < NEXP; e++) {
        acc[e] += __shfl_xor_sync(0xffffffffu, acc[e], 16);
        acc[e] += __shfl_xor_sync(0xffffffffu, acc[e], 8);
        acc[e] += __shfl_xor_sync(0xffffffffu, acc[e], 4);
        acc[e] += __shfl_xor_sync(0xffffffffu, acc[e], 2);
        acc[e] += __shfl_xor_sync(0xffffffffu, acc[e], 1);
    }
    if (lane == 0) {
        if (write_logits) {
#pragma unroll
            for (int e = 0; e < NEXP; e++) logits[(size_t)t * NEXP + e] = acc[e];
        }
        int i0 = 0;
#pragma unroll
        for (int e = 1; e < NEXP; e++) if (acc[e] > acc[i0]) i0 = e;
        int i1 = (i0 == 0) ? 1 : 0;
#pragma unroll
        for (int e = 0; e < NEXP; e++) if (e != i1 && e != i0 && acc[e] > acc[i1]) i1 = e;
        float d  = expf(acc[i1] - acc[i0]);
        float w0 = 1.f / (1.f + d);
        g_te[2*t] = i0;   g_twt[2*t] = w0;
        g_te[2*t+1] = i1; g_twt[2*t+1] = 1.f - w0;
        atomicAdd(&g_counts[i0], 1);
        atomicAdd(&g_counts[i1], 1);
    }
}

__global__ void k_scan() {
    int off = 0, t = 0;
    for (int e = 0; e < NEXP; e++) {
        g_offsets[e] = off;
        int c = g_counts[e];
        for (int r = 0; r < c; r += BM) {
            g_tileE[t] = e; g_tileRow0[t] = off + r;
            g_tileRows[t] = (c - r < BM) ? (c - r) : BM;
            t++;
        }
        off += c;
    }
    g_numTiles = t;
}

__global__ void k_scatter() {
    int t = blockIdx.x * blockDim.x + threadIdx.x;
    if (t >= NTOK) return;
#pragma unroll
    for (int s = 0; s < 2; s++) {
        int e = g_te[2*t + s];
        int pos = g_offsets[e] + atomicAdd(&g_cursors[e], 1);
        g_perm[pos] = t;
        g_wt[pos] = g_twt[2*t + s];
        g_slot[2*t + s] = pos;
    }
}

// ---------------- async chunk issue: 4 operand tiles, 128x32 bf16 each ----------------
template <bool GATHER>
__device__ __forceinline__ void issue_chunk(
    u32 stg, int tid, int k0,
    const __nv_bfloat16* __restrict__ Ah, const __nv_bfloat16* __restrict__ Al,
    size_t a_stride, const int* rowTok, int rows,
    const __nv_bfloat16* __restrict__ Bh, const __nv_bfloat16* __restrict__ Bl,
    size_t b_stride)
{
#pragma unroll
    for (int t4 = 0; t4 < 2; t4++) {
        int u = tid + t4 * 256;          // 0..511 -> 128 rows x 4 16B units
        int m = u >> 2, kb = (u & 3) * 8;
        u32 so = stg + (u32)(m * APITCH + kb) * 2;
        u32 sz; int row;
        if (GATHER) {
            int tok = rowTok[m];
            sz  = (tok >= 0) ? 16u : 0u;
            row = (tok >= 0) ? tok : 0;
        } else {
            sz  = (m < rows) ? 16u : 0u;
            row = (m < rows) ? m : 0;
        }
        size_t ao = (size_t)row * a_stride + k0 + kb;
        cpa16(so + OFF_AH, Ah + ao, sz);
        cpa16(so + OFF_AL, Al + ao, sz);
        size_t bo = (size_t)m * b_stride + k0 + kb;
        cpa16(so + OFF_BH, Bh + bo, 16u);
        cpa16(so + OFF_BL, Bl + bo, 16u);
    }
}

// ---------------- wmma GEMM core: 2-stage cp.async pipeline ----------------
// 8 warps: warp_m in {0,1} x 64 rows, warp_n in {0..3} x 32 cols; 3-term bf16 split.
template <bool GATHER>
__device__ __forceinline__ void gemm_tile(
    char* smem, u32 sb, int tid,
    const __nv_bfloat16* __restrict__ Ah, const __nv_bfloat16* __restrict__ Al,
    size_t a_stride, const int* rowTok, int rows,
    const __nv_bfloat16* __restrict__ Bh, const __nv_bfloat16* __restrict__ Bl,
    size_t b_stride, int kdim,
    wmma::fragment<wmma::accumulator, 16, 16, 16, float> (&acc)[4][2])
{
    int wid = tid >> 5;
    int warp_m = wid & 1, warp_n = wid >> 1;

#pragma unroll
    for (int i = 0; i < 4; i++)
#pragma unroll
        for (int j = 0; j < 2; j++) wmma::fill_fragment(acc[i][j], 0.f);

    u32 stg_a[2] = { sb + SM_STG0, sb + SM_STG0 + STG_SZ };

    // prologue: stage 0
    issue_chunk<GATHER>(stg_a[0], tid, 0, Ah, Al, a_stride, rowTok, rows, Bh, Bl, b_stride);
    cpa_commit();

    int nch = kdim / BK;
    for (int ch = 0; ch < nch; ch++) {
        if (ch + 1 < nch) {
            issue_chunk<GATHER>(stg_a[(ch + 1) & 1], tid, (ch + 1) * BK,
                                Ah, Al, a_stride, rowTok, rows, Bh, Bl, b_stride);
            cpa_commit();
            cpa_wait<1>();
        } else {
            cpa_wait<0>();
        }
        __syncthreads();

        char* stg = smem + SM_STG0 + (ch & 1) * STG_SZ;
        __nv_bfloat16* As_h = (__nv_bfloat16*)(stg + OFF_AH);
        __nv_bfloat16* As_l = (__nv_bfloat16*)(stg + OFF_AL);
        __nv_bfloat16* Bs_h = (__nv_bfloat16*)(stg + OFF_BH);
        __nv_bfloat16* Bs_l = (__nv_bfloat16*)(stg + OFF_BL);

#pragma unroll
        for (int ks = 0; ks < 2; ks++) {
            wmma::fragment<wmma::matrix_b, 16, 16, 16, __nv_bfloat16, wmma::col_major> bh[2], bl[2];
#pragma unroll
            for (int j = 0; j < 2; j++) {
                int n = warp_n * 32 + j * 16;
                wmma::load_matrix_sync(bh[j], Bs_h + (size_t)n * BPITCH + ks * 16, BPITCH);
                wmma::load_matrix_sync(bl[j], Bs_l + (size_t)n * BPITCH + ks * 16, BPITCH);
            }
#pragma unroll
            for (int i = 0; i < 4; i++) {
                int m = warp_m * 64 + i * 16;
                wmma::fragment<wmma::matrix_a, 16, 16, 16, __nv_bfloat16, wmma::row_major> ah, al;
                wmma::load_matrix_sync(ah, As_h + (size_t)m * APITCH + ks * 16, APITCH);
                wmma::load_matrix_sync(al, As_l + (size_t)m * APITCH + ks * 16, APITCH);
#pragma unroll
                for (int j = 0; j < 2; j++) {
                    wmma::mma_sync(acc[i][j], ah, bh[j], acc[i][j]);
                    wmma::mma_sync(acc[i][j], ah, bl[j], acc[i][j]);
                    wmma::mma_sync(acc[i][j], al, bh[j], acc[i][j]);
                }
            }
        }
        __syncthreads();   // protect stage (ch&1) before re-issue at ch+2
    }
}

// ---------------- GEMM1: H1 = gelu(gather(X) @ Wfc[e]^T) ----------------
__global__ __launch_bounds__(256, 2) void k_gemm1(int) {
    int tile = blockIdx.x;
    if (tile >= g_numTiles) return;
    int e = g_tileE[tile], row0 = g_tileRow0[tile], rows = g_tileRows[tile];
    int col0 = blockIdx.y * BN;

    extern __shared__ char smem[];
    u32 sb = smem_u32(smem);
    int tid = threadIdx.x, wid = tid >> 5;
    int warp_m = wid & 1, warp_n = wid >> 1;

    int* rowTok = (int*)(smem + SM_ROWTOK);
    if (tid < BM) rowTok[tid] = (tid < rows) ? g_perm[row0 + tid] : -1;
    __syncthreads();

    wmma::fragment<wmma::accumulator, 16, 16, 16, float> acc[4][2];
    const __nv_bfloat16* Bh = g_Wfh + ((size_t)e * IDIM + col0) * HDIM;
    const __nv_bfloat16* Bl = g_Wfl + ((size_t)e * IDIM + col0) * HDIM;
    gemm_tile<true>(smem, sb, tid, g_Xhi, g_Xlo, HDIM, rowTok, rows, Bh, Bl, HDIM, HDIM, acc);

    float* st = (float*)smem;   // 128 x SPITCH floats (mainloop done; reuse)
    __syncthreads();
#pragma unroll
    for (int i = 0; i < 4; i++)
#pragma unroll
        for (int j = 0; j < 2; j++)
            wmma::store_matrix_sync(st + (size_t)(warp_m * 64 + i * 16) * SPITCH
                                       + warp_n * 32 + j * 16,
                                    acc[i][j], SPITCH, wmma::mem_row_major);
    __syncthreads();
    for (int u = tid; u < 128 * 16; u += 256) {   // 8 bf16 cols per unit
        int m = u >> 4, q = (u & 15) * 8;
        if (m < rows) {
            __nv_bfloat16 h8[8], l8[8];
#pragma unroll
            for (int c = 0; c < 8; c++) {
                float v = st[(size_t)m * SPITCH + q + c];
                float g = 0.5f * v * (1.f + erff(v * 0.70710678118654752f));
                __nv_bfloat16 h = __float2bfloat16(g);
                h8[c] = h;
                l8[c] = __float2bfloat16(g - __bfloat162float(h));
            }
            size_t o = (size_t)(row0 + m) * IDIM + col0 + q;
            *(uint4*)(g_H1h + o) = *(const uint4*)h8;
            *(uint4*)(g_H1l + o) = *(const uint4*)l8;
        }
    }
}

// ---------------- GEMM2: Y2 = H1 @ Wproj[e]^T ----------------
__global__ __launch_bounds__(256, 2) void k_gemm2(int) {
    int tile = blockIdx.x;
    if (tile >= g_numTiles) return;
    int e = g_tileE[tile], row0 = g_tileRow0[tile], rows = g_tileRows[tile];
    int col0 = blockIdx.y * BN;

    extern __shared__ char smem[];
    u32 sb = smem_u32(smem);
    int tid = threadIdx.x, wid = tid >> 5;
    int warp_m = wid & 1, warp_n = wid >> 1;

    wmma::fragment<wmma::accumulator, 16, 16, 16, float> acc[4][2];
    const __nv_bfloat16* Ah = g_H1h + (size_t)row0 * IDIM;
    const __nv_bfloat16* Al = g_H1l + (size_t)row0 * IDIM;
    const __nv_bfloat16* Bh = g_Wph + ((size_t)e * HDIM + col0) * IDIM;
    const __nv_bfloat16* Bl = g_Wpl + ((size_t)e * HDIM + col0) * IDIM;
    gemm_tile<false>(smem, sb, tid, Ah, Al, IDIM, nullptr, rows, Bh, Bl, IDIM, IDIM, acc);

    float* st = (float*)smem;
    __syncthreads();
#pragma unroll
    for (int i = 0; i < 4; i++)
#pragma unroll
        for (int j = 0; j < 2; j++)
            wmma::store_matrix_sync(st + (size_t)(warp_m * 64 + i * 16) * SPITCH
                                       + warp_n * 32 + j * 16,
                                    acc[i][j], SPITCH, wmma::mem_row_major);
    __syncthreads();
    for (int u = tid; u < 128 * 32; u += 256) {   // 4 floats per unit
        int m = u >> 5, q = (u & 31) * 4;
        if (m < rows) {
            size_t o = (size_t)(row0 + m) * HDIM + col0 + q;
            *(uint4*)(g_Y2 + o) = *(const uint4*)(st + (size_t)m * SPITCH + q);
        }
    }
}

// ---------------- combine ----------------
__global__ void k_combine(float* __restrict__ out) {
    int i4 = blockIdx.x * blockDim.x + threadIdx.x;
    if (i4 >= NTOK * (HDIM / 4)) return;
    int t = i4 / (HDIM / 4), h4 = i4 % (HDIM / 4);
    int p0 = g_slot[2*t], p1 = g_slot[2*t + 1];
    float w0 = g_wt[p0], w1 = g_wt[p1];
    float4 a = *(const float4*)(g_Y2 + (size_t)p0 * HDIM + h4 * 4);
    float4 b = *(const float4*)(g_Y2 + (size_t)p1 * HDIM + h4 * 4);
    float4 o;
    o.x = fmaf(w0, a.x, w1 * b.x);
    o.y = fmaf(w0, a.y, w1 * b.y);
    o.z = fmaf(w0, a.z, w1 * b.z);
    o.w = fmaf(w0, a.w, w1 * b.w);
    *((float4*)out + i4) = o;
}

// ---------------- launch ----------------
extern "C" void kernel_launch(void* const* d_in, const int* in_sizes, int n_in,
                              void* d_out, int out_size) {
    const float* X     = (const float*)d_in[0];
    const float* Wg    = (const float*)d_in[1];
    const float* Wfc   = (const float*)d_in[2];
    const float* Wproj = (const float*)d_in[3];
    float* out = (float*)d_out;

    int write_logits = (out_size >= NTOK * HDIM + NTOK * NEXP) ? 1 : 0;
    float* logits = out + (size_t)NTOK * HDIM;

    static int attr_done = 0;
    if (!attr_done) {
        cudaFuncSetAttribute(k_gemm1, cudaFuncAttributeMaxDynamicSharedMemorySize, DSMEM);
        cudaFuncSetAttribute(k_gemm2, cudaFuncAttributeMaxDynamicSharedMemorySize, DSMEM);
        attr_done = 1;
    }

    __nv_bfloat16 *xh, *xl, *wfh, *wfl, *wph, *wpl;
    cudaGetSymbolAddress((void**)&xh,  g_Xhi);  cudaGetSymbolAddress((void**)&xl,  g_Xlo);
    cudaGetSymbolAddress((void**)&wfh, g_Wfh);  cudaGetSymbolAddress((void**)&wfl, g_Wfl);
    cudaGetSymbolAddress((void**)&wph, g_Wph);  cudaGetSymbolAddress((void**)&wpl, g_Wpl);

    k_init<<<1, 32>>>();
    {
        int n4 = NTOK * HDIM / 4;
        k_split<<<(n4 + 255) / 256, 256>>>(X, xh, xl, n4);
    }
    {
        int n4 = NEXP * IDIM * HDIM / 4;
        k_split<<<(n4 + 255) / 256, 256>>>(Wfc, wfh, wfl, n4);
        k_split<<<(n4 + 255) / 256, 256>>>(Wproj, wph, wpl, n4);
    }
    k_router<<<NTOK / 8, 256>>>(X, Wg, logits, write_logits);
    k_scan<<<1, 1>>>();
    k_scatter<<<NTOK / 256, 256>>>();
    k_gemm1<<<dim3(MAXT, IDIM / BN), 256, DSMEM>>>(0);
    k_gemm2<<<dim3(MAXT, HDIM / BN), 256, DSMEM>>>(0);
    k_combine<<<(NTOK * (HDIM / 4) + 255) / 256, 256>>>(out);
}